// round 12
// baseline (speedup 1.0000x reference)
#include <cuda_runtime.h>
#include <cstdint>

#define BB 4
#define SS 512
#define DD 128
#define HH 8
#define SCP 514    // scores pitch: mod 4 == 2 -> q survives bank mod 32 (4-way STS)

// scratch (static device memory; no runtime allocation)
__device__ float g_q[BB*SS*DD];
__device__ float g_k[BB*SS*DD];
__device__ float g_v[BB*SS*DD];
__device__ float g_attn[BB*SS*DD];
__device__ float g_bias[(size_t)BB*SS*HH*SS];   // [b*S+q][h][k]  (h-major, k innermost)

// ---------------- f32x2 helpers ----------------
__device__ __forceinline__ unsigned long long pack2(float x) {
    unsigned long long r;
    asm("mov.b64 %0, {%1, %1};" : "=l"(r) : "f"(x));
    return r;
}
__device__ __forceinline__ unsigned long long pack2v(float lo, float hi) {
    unsigned long long r;
    asm("mov.b64 %0, {%1, %2};" : "=l"(r) : "f"(lo), "f"(hi));
    return r;
}
__device__ __forceinline__ void fma2(unsigned long long& d, unsigned long long a, unsigned long long b) {
    asm("fma.rn.f32x2 %0, %1, %2, %0;" : "+l"(d) : "l"(a), "l"(b));
}
__device__ __forceinline__ void unpack2(unsigned long long v, float& lo, float& hi) {
    asm("mov.b64 {%0, %1}, %2;" : "=f"(lo), "=f"(hi) : "l"(v));
}
__device__ __forceinline__ unsigned int smem_u32(const void* p) {
    return (unsigned int)__cvta_generic_to_shared(p);
}

// ---------------------------------------------------------------------------
// Kernel A: QKV projection with smem-staged weights.
// grid = (128, 3)  [by = matrix], block = 256
// ---------------------------------------------------------------------------
__global__ __launch_bounds__(256) void qkv_kernel(
    const float* __restrict__ x,
    const float* __restrict__ wq, const float* __restrict__ bq,
    const float* __restrict__ wk, const float* __restrict__ bk,
    const float* __restrict__ wv, const float* __restrict__ bv)
{
    extern __shared__ float sm[];
    float* ws = sm;                 // [128][128]
    float (*xs)[128] = (float(*)[128])(sm + 128 * 128);   // [16][128]

    const int t = threadIdx.x;
    const int mat = blockIdx.y;
    const int row0 = blockIdx.x * 16;

    const float* W    = (mat == 0) ? wq : (mat == 1) ? wk : wv;
    const float* bias = (mat == 0) ? bq : (mat == 1) ? bk : bv;
    float* out        = (mat == 0) ? g_q : (mat == 1) ? g_k : g_v;

    #pragma unroll
    for (int i = t; i < 4096; i += 256)
        ((float4*)ws)[i] = ((const float4*)W)[i];
    #pragma unroll
    for (int i = t; i < 512; i += 256)
        ((float4*)xs)[i] = ((const float4*)(x + (size_t)row0 * DD))[i];
    __syncthreads();

    const int c4 = t & 31;
    const int rg = t >> 5;
    const ulonglong2* W2 = (const ulonglong2*)ws;

    unsigned long long acc[2][2];
    acc[0][0] = acc[0][1] = acc[1][0] = acc[1][1] = 0ull;

    #pragma unroll 8
    for (int d = 0; d < 128; d++) {
        ulonglong2 w = W2[d * 32 + c4];
        #pragma unroll
        for (int r = 0; r < 2; r++) {
            unsigned long long xr = pack2(xs[rg * 2 + r][d]);
            fma2(acc[r][0], xr, w.x);
            fma2(acc[r][1], xr, w.y);
        }
    }
    float4 bb = ((const float4*)bias)[c4];
    #pragma unroll
    for (int r = 0; r < 2; r++) {
        float4 o;
        unpack2(acc[r][0], o.x, o.y);
        unpack2(acc[r][1], o.z, o.w);
        o.x += bb.x; o.y += bb.y; o.z += bb.z; o.w += bb.w;
        ((float4*)(out + (size_t)(row0 + rg * 2 + r) * DD))[c4] = o;
    }
}

// ---------------------------------------------------------------------------
// Kernel B: st_bias stream — 4 rows/lane d-slabs, 2-deep cp.async pipeline.
// (R10 structure; output now TRANSPOSED to [bq][h][k] for coalesced attn reads)
// block = 256 (8 warps), grid = 148, smem = 4KB weights + 160KB stage
// ---------------------------------------------------------------------------
#define BIAS_GRID 148
#define SLAB_PITCH 20                 // floats per slab row (16 d + 4 pad)
#define SLAB_F (128 * SLAB_PITCH)     // 2560 floats = 10240 B per buffer
#define N_TASKS 8192                  // 1,048,576 rows / 128
__global__ __launch_bounds__(256) void bias_kernel(
    const float* __restrict__ st, const float* __restrict__ wst)
{
    extern __shared__ float sm[];
    unsigned long long* wp = (unsigned long long*)sm;   // [64 d-pairs][8 heads] u64
    float* stage = sm + 1024;                            // 8 warps x 2 bufs x SLAB_F

    const int tid  = threadIdx.x;
    const int lane = tid & 31;
    const int wid  = tid >> 5;

    // weight table: wp[j*8+h] = (wst[2j][h], wst[2j+1][h])
    for (int idx = tid; idx < 512; idx += 256) {
        int j = idx >> 3, h = idx & 7;
        wp[idx] = pack2v(wst[(2 * j) * HH + h], wst[(2 * j + 1) * HH + h]);
    }
    __syncthreads();

    float* buf0 = stage + wid * (2 * SLAB_F);
    const unsigned bufu = smem_u32(buf0);

    const int prow = lane >> 2;   // 0..7 (row-in-group for staging)
    const int pchk = lane & 3;    // 16B chunk within the 64B slab-row

    // stage one slab: 128 rows x 64 B, 16 cp.async warp-instr
    #define PREF(row0_, s_, b_) do {                                                 \
        const char* gsrc = (const char*)st + ((size_t)(row0_) + prow) * 512          \
                           + (s_) * 64 + pchk * 16;                                  \
        unsigned sdst = bufu + (b_) * (SLAB_F * 4) + prow * 80 + pchk * 16;          \
        _Pragma("unroll")                                                            \
        for (int i = 0; i < 16; i++)                                                 \
            asm volatile("cp.async.cg.shared.global [%0], [%1], 16;"                 \
                         :: "r"(sdst + i * 8 * 80), "l"(gsrc + (size_t)i * 8 * 512)  \
                         : "memory");                                                \
        asm volatile("cp.async.commit_group;");                                      \
    } while (0)

    const unsigned NW = BIAS_GRID * 8;   // 1184 warps
    unsigned task = blockIdx.x * 8 + wid;

    PREF((size_t)task * 128, 0, 0);
    int buf = 0;

    for (; task < N_TASKS; task += NW) {
        const size_t row0 = (size_t)task * 128;
        unsigned long long acc[4][8];
        #pragma unroll
        for (int r = 0; r < 4; r++)
            #pragma unroll
            for (int h = 0; h < 8; h++) acc[r][h] = 0ull;

        for (int s = 0; s < 8; s++) {
            if (s < 7) {
                PREF(row0, s + 1, buf ^ 1);
            } else {
                const unsigned nt = task + NW;
                const size_t nr0 = (nt < N_TASKS) ? (size_t)nt * 128 : row0;
                PREF(nr0, 0, buf ^ 1);
            }
            asm volatile("cp.async.wait_group 1;" ::: "memory");
            __syncwarp();

            const float* slab = buf0 + buf * SLAB_F;
            const unsigned long long* wslab = wp + s * 64;   // 8 d-pairs x 8 heads

            #pragma unroll
            for (int q = 0; q < 4; q++) {            // float4 (= 2 d-pairs) index
                ulonglong2 e[4];
                #pragma unroll
                for (int r = 0; r < 4; r++)
                    e[r] = *(const ulonglong2*)(slab + (lane + 32 * r) * SLAB_PITCH + q * 4);
                const unsigned long long* w0 = wslab + (2 * q) * 8;
                #pragma unroll
                for (int h = 0; h < 8; h++) {
                    const unsigned long long wv = w0[h];
                    fma2(acc[0][h], e[0].x, wv);
                    fma2(acc[1][h], e[1].x, wv);
                    fma2(acc[2][h], e[2].x, wv);
                    fma2(acc[3][h], e[3].x, wv);
                }
                const unsigned long long* w1 = wslab + (2 * q + 1) * 8;
                #pragma unroll
                for (int h = 0; h < 8; h++) {
                    const unsigned long long wv = w1[h];
                    fma2(acc[0][h], e[0].y, wv);
                    fma2(acc[1][h], e[1].y, wv);
                    fma2(acc[2][h], e[2].y, wv);
                    fma2(acc[3][h], e[3].y, wv);
                }
            }
            __syncwarp();    // all lanes done reading buf before it is re-prefetched
            buf ^= 1;
        }

        #pragma unroll
        for (int r = 0; r < 4; r++) {
            const size_t row = row0 + lane + 32 * r;   // flattened bq*512 + k
            const size_t bq = row >> 9;
            const int k = (int)(row & 511);
            #pragma unroll
            for (int h = 0; h < 8; h++) {
                float lo, hi;
                unpack2(acc[r][h], lo, hi);
                g_bias[(bq * HH + h) * SS + k] = lo + hi;   // coalesced across lanes
            }
        }
    }
    #undef PREF
}

// ---------------------------------------------------------------------------
// Kernel C: attention. grid = 256 (b = bx>>6, q0 = (bx&63)*8), block = 512.
// Phase 1: no K staging — warp (h, g), lane (q, ksub); Q in regs; K via LDG.128
// with 8-lane q-broadcast. Bias added during softmax (coalesced LDG stream).
// ---------------------------------------------------------------------------
__global__ __launch_bounds__(512, 1) void attn_kernel(const int* __restrict__ mask)
{
    extern __shared__ float smem[];
    float* scores = smem;                       // [64][SCP]
    float* qs     = scores + 64 * SCP;          // [8][132]
    float* mask_s = qs + 8 * 132;               // [512]
    float* rinv_s = mask_s + 512;               // [64] (q*8+h)
    float* outp   = rinv_s + 64;                // [2][8][8][16]

    const int tid  = threadIdx.x;
    const int lane = tid & 31;
    const int wid  = tid >> 5;
    const int b    = blockIdx.x >> 6;
    const int q0   = (blockIdx.x & 63) * 8;

    if (tid < 256) {
        int r = tid >> 5, c4 = tid & 31;
        *(float4*)(qs + r * 132 + c4 * 4) =
            ((const float4*)(g_q + (size_t)(b * SS + q0 + r) * DD))[c4];
    }
    mask_s[tid] = mask[b * SS + tid] ? -10000.0f : 0.0f;
    __syncthreads();

    // ---------------- Phase 1: scores = qk/4 (raw; bias added in softmax) ----
    {
        const int h = wid & 7, g = wid >> 3;     // warp = (head, k-half)
        const int q = lane >> 2, ksub = lane & 3;

        const float* qrow = qs + q * 132 + h * 16;
        ulonglong2 qc[4];
        #pragma unroll
        for (int e = 0; e < 4; e++) qc[e] = *(const ulonglong2*)(qrow + e * 4);

        const float* kbase = g_k + (size_t)(b * SS + g * 256 + ksub) * DD + h * 16;
        float* srow = scores + (q * 8 + h) * SCP + g * 256 + ksub;

        #pragma unroll 4
        for (int i = 0; i < 64; i++) {
            const ulonglong2* kr = (const ulonglong2*)(kbase + (size_t)(4 * i) * DD);
            unsigned long long a0 = 0ull, a1 = 0ull;
            #pragma unroll
            for (int e = 0; e < 4; e++) {
                ulonglong2 kc2 = kr[e];          // 8-lane broadcast across q
                fma2(a0, kc2.x, qc[e].x);
                fma2(a1, kc2.y, qc[e].y);
            }
            float l0, h0_, l1, h1_;
            unpack2(a0, l0, h0_);
            unpack2(a1, l1, h1_);
            srow[4 * i] = (l0 + h0_ + l1 + h1_) * 0.25f;
        }
    }
    __syncthreads();

    // ---------------- Phase 2: softmax per (q,h) row, bias fused ----------------
    for (int rr = wid; rr < 64; rr += 16) {
        const int q = rr >> 3, h = rr & 7;
        float* srow = scores + rr * SCP;
        const float* brow = g_bias + ((size_t)(b * SS + q0 + q) * HH + h) * SS;
        float vals[16];
        float mx = -1e30f;
        #pragma unroll
        for (int j = 0; j < 16; j++) {
            int k = lane + 32 * j;
            float v = srow[k] + __ldg(brow + k) + mask_s[k];
            vals[j] = v;
            mx = fmaxf(mx, v);
        }
        #pragma unroll
        for (int o = 16; o > 0; o >>= 1) mx = fmaxf(mx, __shfl_xor_sync(0xffffffffu, mx, o));
        float sum = 0.f;
        #pragma unroll
        for (int j = 0; j < 16; j++) {
            float e = __expf(vals[j] - mx);
            srow[lane + 32 * j] = e;
            sum += e;
        }
        #pragma unroll
        for (int o = 16; o > 0; o >>= 1) sum += __shfl_xor_sync(0xffffffffu, sum, o);
        if (lane == 0) rinv_s[rr] = 1.0f / sum;
    }
    __syncthreads();

    // ---------------- Phase 3: PV (f32x2 over k-pairs, probs via LDS.64) ----
    {
        const int h   = wid & 7;
        const int ks2 = wid >> 3;      // k-half
        const int e   = lane & 15;
        const int kk  = lane >> 4;     // 0/1
        const float* vbase = g_v + (size_t)(b * SS) * DD + h * 16 + e;
        const float* sbase = scores + h * SCP;

        unsigned long long acc2[8];
        #pragma unroll
        for (int q = 0; q < 8; q++) acc2[q] = 0ull;

        const int kstart = ks2 * 256 + kk * 4;
        #pragma unroll 4
        for (int i = 0; i < 32; i++) {
            const int k4 = kstart + i * 8;
            float v0 = vbase[(size_t)(k4 + 0) * DD];
            float v1 = vbase[(size_t)(k4 + 1) * DD];
            float v2 = vbase[(size_t)(k4 + 2) * DD];
            float v3 = vbase[(size_t)(k4 + 3) * DD];
            unsigned long long vp01 = pack2v(v0, v1);
            unsigned long long vp23 = pack2v(v2, v3);
            #pragma unroll
            for (int q = 0; q < 8; q++) {
                const float* p = sbase + q * 8 * SCP + k4;   // 8B-aligned (SCP even)
                unsigned long long pa = *(const unsigned long long*)p;
                unsigned long long pb = *(const unsigned long long*)(p + 2);
                fma2(acc2[q], pa, vp01);
                fma2(acc2[q], pb, vp23);
            }
        }
        #pragma unroll
        for (int q = 0; q < 8; q++) {
            float lo, hi;
            unpack2(acc2[q], lo, hi);
            float s = lo + hi;
            s += __shfl_xor_sync(0xffffffffu, s, 16);
            if (lane < 16)
                outp[((ks2 * 8 + h) * 8 + q) * 16 + e] = s;
        }
    }
    __syncthreads();

    #pragma unroll
    for (int id = tid; id < 1024; id += 512) {
        int e = id & 15, q = (id >> 4) & 7, h = id >> 7;
        float val = (outp[((0 * 8 + h) * 8 + q) * 16 + e] +
                     outp[((1 * 8 + h) * 8 + q) * 16 + e]) * rinv_s[q * 8 + h];
        g_attn[(size_t)(b * SS + q0 + q) * DD + h * 16 + e] = val;
    }
}

// ---------------------------------------------------------------------------
// Kernel D: out = LN(residual + attn @ wo + bo), smem-staged wo.
// grid=128 (16 rows), block=256   (R10 best-known config)
// ---------------------------------------------------------------------------
__global__ __launch_bounds__(256) void out_ln_kernel(
    const float* __restrict__ x, const float* __restrict__ wo,
    const float* __restrict__ bo, const float* __restrict__ g,
    const float* __restrict__ bbeta, float* __restrict__ out)
{
    extern __shared__ float sm[];
    float* ws = sm;                                         // [128][128]
    float (*as_)[128] = (float(*)[128])(sm + 128 * 128);    // [16][128]
    float (*ys)[128]  = (float(*)[128])(sm + 128 * 128 + 16 * 128); // [16][128]

    const int row0 = blockIdx.x * 16;
    const int t = threadIdx.x;

    #pragma unroll
    for (int i = t; i < 4096; i += 256)
        ((float4*)ws)[i] = ((const float4*)wo)[i];
    #pragma unroll
    for (int i = t; i < 512; i += 256)
        ((float4*)as_)[i] = ((const float4*)(g_attn + (size_t)row0 * DD))[i];
    __syncthreads();

    const int c4 = t & 31;
    const int rg = t >> 5;   // rows rg*2, rg*2+1
    const ulonglong2* W2 = (const ulonglong2*)ws;

    unsigned long long acc[2][2];
    acc[0][0] = acc[0][1] = acc[1][0] = acc[1][1] = 0ull;

    #pragma unroll 8
    for (int d = 0; d < 128; d++) {
        ulonglong2 w = W2[d * 32 + c4];
        #pragma unroll
        for (int r = 0; r < 2; r++) {
            unsigned long long xr = pack2(as_[rg * 2 + r][d]);
            fma2(acc[r][0], xr, w.x);
            fma2(acc[r][1], xr, w.y);
        }
    }
    float4 bb = ((const float4*)bo)[c4];
    #pragma unroll
    for (int r = 0; r < 2; r++) {
        float4 o;
        unpack2(acc[r][0], o.x, o.y);
        unpack2(acc[r][1], o.z, o.w);
        float4 xr = ((const float4*)(x + (size_t)(row0 + rg * 2 + r) * DD))[c4];
        o.x += bb.x + xr.x; o.y += bb.y + xr.y;
        o.z += bb.z + xr.z; o.w += bb.w + xr.w;
        ((float4*)ys[rg * 2 + r])[c4] = o;
    }
    __syncthreads();

    // LayerNorm: 8 warps x 2 rows
    const int wid = t >> 5, lane = t & 31;
    #pragma unroll
    for (int r = 0; r < 2; r++) {
        const int row = wid * 2 + r;
        float4 v = ((float4*)ys[row])[lane];
        float s = v.x + v.y + v.z + v.w;
        #pragma unroll
        for (int o = 16; o > 0; o >>= 1) s += __shfl_xor_sync(0xffffffffu, s, o);
        float mu = s * (1.f / 128.f);
        float dx = v.x - mu, dy = v.y - mu, dz = v.z - mu, dw = v.w - mu;
        float ss = dx * dx + dy * dy + dz * dz + dw * dw;
        #pragma unroll
        for (int o = 16; o > 0; o >>= 1) ss += __shfl_xor_sync(0xffffffffu, ss, o);
        float rstd = rsqrtf(ss * (1.f / 128.f) + 1e-5f);
        float4 gg = ((const float4*)g)[lane];
        float4 bb2 = ((const float4*)bbeta)[lane];
        float4 o4;
        o4.x = dx * rstd * gg.x + bb2.x;
        o4.y = dy * rstd * gg.y + bb2.y;
        o4.z = dz * rstd * gg.z + bb2.z;
        o4.w = dw * rstd * gg.w + bb2.w;
        ((float4*)(out + (size_t)(row0 + row) * DD))[lane] = o4;
    }
}

// ---------------------------------------------------------------------------
extern "C" void kernel_launch(void* const* d_in, const int* in_sizes, int n_in,
                              void* d_out, int out_size)
{
    const float* x    = (const float*)d_in[0];
    const float* st   = (const float*)d_in[1];
    const int*   mask = (const int*)  d_in[2];
    const float* wq   = (const float*)d_in[3];
    const float* bq   = (const float*)d_in[4];
    const float* wk   = (const float*)d_in[5];
    const float* bk   = (const float*)d_in[6];
    const float* wv   = (const float*)d_in[7];
    const float* bv   = (const float*)d_in[8];
    const float* wo   = (const float*)d_in[9];
    const float* bo   = (const float*)d_in[10];
    const float* wst  = (const float*)d_in[11];
    const float* lng  = (const float*)d_in[12];
    const float* lnb  = (const float*)d_in[13];
    float* out = (float*)d_out;

    const int SMEM_BIAS = 4096 + 8 * 2 * SLAB_F * 4;                           // 167936 B
    const int SMEM_QKV  = (128 * 128 + 16 * 128) * 4;                          // 73728 B
    const int SMEM_ATTN = (64 * SCP + 8 * 132 + 512 + 64 + 2048) * 4;          // 146304 B
    const int SMEM_OLN  = (128 * 128 + 16 * 128 + 16 * 128) * 4;               // 81920 B
    cudaFuncSetAttribute(bias_kernel, cudaFuncAttributeMaxDynamicSharedMemorySize, SMEM_BIAS);
    cudaFuncSetAttribute(qkv_kernel,  cudaFuncAttributeMaxDynamicSharedMemorySize, SMEM_QKV);
    cudaFuncSetAttribute(attn_kernel, cudaFuncAttributeMaxDynamicSharedMemorySize, SMEM_ATTN);
    cudaFuncSetAttribute(out_ln_kernel, cudaFuncAttributeMaxDynamicSharedMemorySize, SMEM_OLN);

    bias_kernel<<<BIAS_GRID, 256, SMEM_BIAS>>>(st, wst);
    qkv_kernel<<<dim3(128, 3), 256, SMEM_QKV>>>(x, wq, bq, wk, bk, wv, bv);
    attn_kernel<<<256, 512, SMEM_ATTN>>>(mask);
    out_ln_kernel<<<128, 256, SMEM_OLN>>>(x, wo, bo, lng, lnb, out);
}

// round 13
// speedup vs baseline: 1.2984x; 1.2984x over previous
#include <cuda_runtime.h>
#include <cstdint>

#define BB 4
#define SS 512
#define DD 128
#define HH 8
#define SC_PITCH 516

// scratch (static device memory; no runtime allocation)
__device__ float g_q[BB*SS*DD];
__device__ float g_k[BB*SS*DD];
__device__ float g_v[BB*SS*DD];
__device__ float g_attn[BB*SS*DD];
__device__ float g_bias[(size_t)BB*SS*SS*HH];   // [b*S+q][k][h], h innermost

// ---------------- f32x2 helpers ----------------
__device__ __forceinline__ unsigned long long pack2(float x) {
    unsigned long long r;
    asm("mov.b64 %0, {%1, %1};" : "=l"(r) : "f"(x));
    return r;
}
__device__ __forceinline__ unsigned long long pack2v(float lo, float hi) {
    unsigned long long r;
    asm("mov.b64 %0, {%1, %2};" : "=l"(r) : "f"(lo), "f"(hi));
    return r;
}
__device__ __forceinline__ void fma2(unsigned long long& d, unsigned long long a, unsigned long long b) {
    asm("fma.rn.f32x2 %0, %1, %2, %0;" : "+l"(d) : "l"(a), "l"(b));
}
__device__ __forceinline__ void unpack2(unsigned long long v, float& lo, float& hi) {
    asm("mov.b64 {%0, %1}, %2;" : "=f"(lo), "=f"(hi) : "l"(v));
}
__device__ __forceinline__ unsigned int smem_u32(const void* p) {
    return (unsigned int)__cvta_generic_to_shared(p);
}

// ---------------------------------------------------------------------------
// Kernel A: QKV projection with smem-staged weights.
// grid = (128, 3)  [by = matrix], block = 256
// ---------------------------------------------------------------------------
__global__ __launch_bounds__(256) void qkv_kernel(
    const float* __restrict__ x,
    const float* __restrict__ wq, const float* __restrict__ bq,
    const float* __restrict__ wk, const float* __restrict__ bk,
    const float* __restrict__ wv, const float* __restrict__ bv)
{
    extern __shared__ float sm[];
    float* ws = sm;                 // [128][128]
    float (*xs)[128] = (float(*)[128])(sm + 128 * 128);   // [16][128]

    const int t = threadIdx.x;
    const int mat = blockIdx.y;
    const int row0 = blockIdx.x * 16;

    const float* W    = (mat == 0) ? wq : (mat == 1) ? wk : wv;
    const float* bias = (mat == 0) ? bq : (mat == 1) ? bk : bv;
    float* out        = (mat == 0) ? g_q : (mat == 1) ? g_k : g_v;

    #pragma unroll
    for (int i = t; i < 4096; i += 256)
        ((float4*)ws)[i] = ((const float4*)W)[i];
    #pragma unroll
    for (int i = t; i < 512; i += 256)
        ((float4*)xs)[i] = ((const float4*)(x + (size_t)row0 * DD))[i];
    __syncthreads();

    const int c4 = t & 31;
    const int rg = t >> 5;
    const ulonglong2* W2 = (const ulonglong2*)ws;

    unsigned long long acc[2][2];
    acc[0][0] = acc[0][1] = acc[1][0] = acc[1][1] = 0ull;

    #pragma unroll 8
    for (int d = 0; d < 128; d++) {
        ulonglong2 w = W2[d * 32 + c4];
        #pragma unroll
        for (int r = 0; r < 2; r++) {
            unsigned long long xr = pack2(xs[rg * 2 + r][d]);
            fma2(acc[r][0], xr, w.x);
            fma2(acc[r][1], xr, w.y);
        }
    }
    float4 bb = ((const float4*)bias)[c4];
    #pragma unroll
    for (int r = 0; r < 2; r++) {
        float4 o;
        unpack2(acc[r][0], o.x, o.y);
        unpack2(acc[r][1], o.z, o.w);
        o.x += bb.x; o.y += bb.y; o.z += bb.z; o.w += bb.w;
        ((float4*)(out + (size_t)(row0 + rg * 2 + r) * DD))[c4] = o;
    }
}

// ---------------------------------------------------------------------------
// Kernel B: st_bias stream — 4 rows/lane d-slabs, 2-deep cp.async pipeline.
// (exact R10 version; output [row][h])
// block = 256 (8 warps), grid = 148, smem = 4KB weights + 160KB stage
// ---------------------------------------------------------------------------
#define BIAS_GRID 148
#define SLAB_PITCH 20                 // floats per slab row (16 d + 4 pad)
#define SLAB_F (128 * SLAB_PITCH)     // 2560 floats = 10240 B per buffer
#define N_TASKS 8192                  // 1,048,576 rows / 128
__global__ __launch_bounds__(256) void bias_kernel(
    const float* __restrict__ st, const float* __restrict__ wst)
{
    extern __shared__ float sm[];
    unsigned long long* wp = (unsigned long long*)sm;   // [64 d-pairs][8 heads] u64
    float* stage = sm + 1024;                            // 8 warps x 2 bufs x SLAB_F

    const int tid  = threadIdx.x;
    const int lane = tid & 31;
    const int wid  = tid >> 5;

    // weight table: wp[j*8+h] = (wst[2j][h], wst[2j+1][h])
    for (int idx = tid; idx < 512; idx += 256) {
        int j = idx >> 3, h = idx & 7;
        wp[idx] = pack2v(wst[(2 * j) * HH + h], wst[(2 * j + 1) * HH + h]);
    }
    __syncthreads();

    float* buf0 = stage + wid * (2 * SLAB_F);
    const unsigned bufu = smem_u32(buf0);

    const int prow = lane >> 2;   // 0..7 (row-in-group for staging)
    const int pchk = lane & 3;    // 16B chunk within the 64B slab-row

    // stage one slab: 128 rows x 64 B, 16 cp.async warp-instr
    #define PREF(row0_, s_, b_) do {                                                 \
        const char* gsrc = (const char*)st + ((size_t)(row0_) + prow) * 512          \
                           + (s_) * 64 + pchk * 16;                                  \
        unsigned sdst = bufu + (b_) * (SLAB_F * 4) + prow * 80 + pchk * 16;          \
        _Pragma("unroll")                                                            \
        for (int i = 0; i < 16; i++)                                                 \
            asm volatile("cp.async.cg.shared.global [%0], [%1], 16;"                 \
                         :: "r"(sdst + i * 8 * 80), "l"(gsrc + (size_t)i * 8 * 512)  \
                         : "memory");                                                \
        asm volatile("cp.async.commit_group;");                                      \
    } while (0)

    const unsigned NW = BIAS_GRID * 8;   // 1184 warps
    unsigned task = blockIdx.x * 8 + wid;

    PREF((size_t)task * 128, 0, 0);
    int buf = 0;

    for (; task < N_TASKS; task += NW) {
        const size_t row0 = (size_t)task * 128;
        unsigned long long acc[4][8];
        #pragma unroll
        for (int r = 0; r < 4; r++)
            #pragma unroll
            for (int h = 0; h < 8; h++) acc[r][h] = 0ull;

        for (int s = 0; s < 8; s++) {
            if (s < 7) {
                PREF(row0, s + 1, buf ^ 1);
            } else {
                const unsigned nt = task + NW;
                const size_t nr0 = (nt < N_TASKS) ? (size_t)nt * 128 : row0;
                PREF(nr0, 0, buf ^ 1);
            }
            asm volatile("cp.async.wait_group 1;" ::: "memory");
            __syncwarp();

            const float* slab = buf0 + buf * SLAB_F;
            const unsigned long long* wslab = wp + s * 64;   // 8 d-pairs x 8 heads

            #pragma unroll
            for (int q = 0; q < 4; q++) {            // float4 (= 2 d-pairs) index
                ulonglong2 e[4];
                #pragma unroll
                for (int r = 0; r < 4; r++)
                    e[r] = *(const ulonglong2*)(slab + (lane + 32 * r) * SLAB_PITCH + q * 4);
                const unsigned long long* w0 = wslab + (2 * q) * 8;
                #pragma unroll
                for (int h = 0; h < 8; h++) {
                    const unsigned long long wv = w0[h];
                    fma2(acc[0][h], e[0].x, wv);
                    fma2(acc[1][h], e[1].x, wv);
                    fma2(acc[2][h], e[2].x, wv);
                    fma2(acc[3][h], e[3].x, wv);
                }
                const unsigned long long* w1 = wslab + (2 * q + 1) * 8;
                #pragma unroll
                for (int h = 0; h < 8; h++) {
                    const unsigned long long wv = w1[h];
                    fma2(acc[0][h], e[0].y, wv);
                    fma2(acc[1][h], e[1].y, wv);
                    fma2(acc[2][h], e[2].y, wv);
                    fma2(acc[3][h], e[3].y, wv);
                }
            }
            __syncwarp();    // all lanes done reading buf before it is re-prefetched
            buf ^= 1;
        }

        #pragma unroll
        for (int r = 0; r < 4; r++) {
            float o[8];
            #pragma unroll
            for (int h = 0; h < 8; h++) {
                float lo, hi;
                unpack2(acc[r][h], lo, hi);
                o[h] = lo + hi;
            }
            float* dst = g_bias + (row0 + lane + 32 * r) * HH;
            *(float4*)dst       = make_float4(o[0], o[1], o[2], o[3]);
            *(float4*)(dst + 4) = make_float4(o[4], o[5], o[6], o[7]);
        }
    }
    #undef PREF
}

// ---------------------------------------------------------------------------
// Kernel C: attention (qk + bias + mask + softmax + PV).
// grid = 256 (b = bx>>6, q0 = (bx&63)*8), block = 512.
// Phase 1: thread = (g, q2, kl) computes 2 q-rows per K row -> K crossbar
// traffic halved, q loads are warp-broadcast, 4 stage iterations.
// ---------------------------------------------------------------------------
__global__ __launch_bounds__(512, 1) void attn_kernel(const int* __restrict__ mask)
{
    extern __shared__ float smem[];
    float* scores = smem;                               // [64][SC_PITCH]
    float* qs     = scores + 64 * SC_PITCH;             // [8][128]
    float* mask_s = qs + 8 * 128;                       // [512]
    float* rinv_s = mask_s + 512;                       // [64] (q*8+h)
    float* ks     = rinv_s + 64;                        // [128][132]; reused as outp[2][8][8][16]

    const int tid  = threadIdx.x;
    const int lane = tid & 31;
    const int wid  = tid >> 5;
    const int b    = blockIdx.x >> 6;
    const int q0   = (blockIdx.x & 63) * 8;

    if (tid < 256)
        ((float4*)qs)[tid] = ((const float4*)(g_q + (size_t)(b * SS + q0) * DD))[tid];
    mask_s[tid] = mask[b * SS + tid] ? -10000.0f : 0.0f;
    __syncthreads();

    // ---------------- Phase 1: scores = qk/4 + bias (2 q per thread) --------
    {
        const int g  = tid >> 8;          // 0/1: which 64-row half of the chunk
        const int q2 = (tid >> 6) & 3;    // q pair index
        const int kl = tid & 63;          // k row within half

        for (int c = 0; c < 4; c++) {
            // stage 128 K rows (chunks 2c, 2c+1), pitch 33 float4
            const float4* kg = (const float4*)(g_k + (size_t)(b * SS + c * 128) * DD);
            #pragma unroll
            for (int idx = tid; idx < 128 * 32; idx += 512)
                ((float4*)ks)[(idx >> 5) * 33 + (idx & 31)] = kg[idx];
            __syncthreads();

            unsigned long long acc2[2][8];
            #pragma unroll
            for (int r = 0; r < 2; r++)
                #pragma unroll
                for (int h = 0; h < 8; h++) acc2[r][h] = 0ull;

            const ulonglong2* kr  = (const ulonglong2*)(ks + (g * 64 + kl) * 132);
            const ulonglong2* qr0 = (const ulonglong2*)(qs + (q2 * 2) * 128);
            const ulonglong2* qr1 = (const ulonglong2*)(qs + (q2 * 2 + 1) * 128);
            #pragma unroll
            for (int j = 0; j < 32; j++) {
                ulonglong2 kk2 = kr[j];        // conflict-free (stride 132)
                ulonglong2 a0  = qr0[j];       // warp-broadcast
                ulonglong2 a1  = qr1[j];       // warp-broadcast
                fma2(acc2[0][j >> 2], a0.x, kk2.x);
                fma2(acc2[0][j >> 2], a0.y, kk2.y);
                fma2(acc2[1][j >> 2], a1.x, kk2.x);
                fma2(acc2[1][j >> 2], a1.y, kk2.y);
            }

            const int kidx = c * 128 + g * 64 + kl;
            #pragma unroll
            for (int r = 0; r < 2; r++) {
                const int q = q2 * 2 + r;
                const float4* brow = (const float4*)(g_bias +
                    ((size_t)(b * SS + q0 + q) * SS + kidx) * HH);
                float4 b0 = __ldg(brow);
                float4 b1 = __ldg(brow + 1);
                float bh[8] = {b0.x, b0.y, b0.z, b0.w, b1.x, b1.y, b1.z, b1.w};

                float* sdst = scores + (q * 8) * SC_PITCH + kidx;
                #pragma unroll
                for (int h = 0; h < 8; h++) {
                    float lo, hi;
                    unpack2(acc2[r][h], lo, hi);
                    sdst[h * SC_PITCH] = fmaf(lo + hi, 0.25f, bh[h]);
                }
            }
            __syncthreads();
        }
    }

    // ---------------- Phase 2: softmax per (q,h) row ----------------
    for (int rr = wid; rr < 64; rr += 16) {
        float* srow = scores + rr * SC_PITCH;
        float vals[16];
        float mx = -1e30f;
        #pragma unroll
        for (int j = 0; j < 16; j++) {
            int k = lane + 32 * j;
            float v = srow[k] + mask_s[k];
            vals[j] = v;
            mx = fmaxf(mx, v);
        }
        #pragma unroll
        for (int o = 16; o > 0; o >>= 1) mx = fmaxf(mx, __shfl_xor_sync(0xffffffffu, mx, o));
        float sum = 0.f;
        #pragma unroll
        for (int j = 0; j < 16; j++) {
            float e = __expf(vals[j] - mx);
            srow[lane + 32 * j] = e;
            sum += e;
        }
        #pragma unroll
        for (int o = 16; o > 0; o >>= 1) sum += __shfl_xor_sync(0xffffffffu, sum, o);
        if (lane == 0) rinv_s[rr] = 1.0f / sum;
    }
    __syncthreads();

    // ---------------- Phase 3: PV (f32x2 over k-pairs, probs via LDS.128) ----
    float* outp = ks;   // reuse: [2][8][8][16]
    {
        const int h   = wid & 7;
        const int ks2 = wid >> 3;      // k-half
        const int e   = lane & 15;
        const int kk  = lane >> 4;     // 0/1
        const float* vbase = g_v + (size_t)(b * SS) * DD + h * 16 + e;
        const float* sbase = scores + h * SC_PITCH;

        unsigned long long acc2[8];
        #pragma unroll
        for (int q = 0; q < 8; q++) acc2[q] = 0ull;

        const int kstart = ks2 * 256 + kk * 4;
        #pragma unroll 4
        for (int i = 0; i < 32; i++) {
            const int k4 = kstart + i * 8;
            float v0 = vbase[(size_t)(k4 + 0) * DD];
            float v1 = vbase[(size_t)(k4 + 1) * DD];
            float v2 = vbase[(size_t)(k4 + 2) * DD];
            float v3 = vbase[(size_t)(k4 + 3) * DD];
            unsigned long long vp01 = pack2v(v0, v1);
            unsigned long long vp23 = pack2v(v2, v3);
            #pragma unroll
            for (int q = 0; q < 8; q++) {
                ulonglong2 p2 = *(const ulonglong2*)(sbase + q * 8 * SC_PITCH + k4);
                fma2(acc2[q], p2.x, vp01);
                fma2(acc2[q], p2.y, vp23);
            }
        }
        #pragma unroll
        for (int q = 0; q < 8; q++) {
            float lo, hi;
            unpack2(acc2[q], lo, hi);
            float s = lo + hi;
            s += __shfl_xor_sync(0xffffffffu, s, 16);
            if (lane < 16)
                outp[((ks2 * 8 + h) * 8 + q) * 16 + e] = s;
        }
    }
    __syncthreads();

    #pragma unroll
    for (int id = tid; id < 1024; id += 512) {
        int e = id & 15, q = (id >> 4) & 7, h = id >> 7;
        float val = (outp[((0 * 8 + h) * 8 + q) * 16 + e] +
                     outp[((1 * 8 + h) * 8 + q) * 16 + e]) * rinv_s[q * 8 + h];
        g_attn[(size_t)(b * SS + q0 + q) * DD + h * 16 + e] = val;
    }
}

// ---------------------------------------------------------------------------
// Kernel D: out = LN(residual + attn @ wo + bo), smem-staged wo.
// grid=128 (16 rows), block=256   (R10 config)
// ---------------------------------------------------------------------------
__global__ __launch_bounds__(256) void out_ln_kernel(
    const float* __restrict__ x, const float* __restrict__ wo,
    const float* __restrict__ bo, const float* __restrict__ g,
    const float* __restrict__ bbeta, float* __restrict__ out)
{
    extern __shared__ float sm[];
    float* ws = sm;                                         // [128][128]
    float (*as_)[128] = (float(*)[128])(sm + 128 * 128);    // [16][128]
    float (*ys)[128]  = (float(*)[128])(sm + 128 * 128 + 16 * 128); // [16][128]

    const int row0 = blockIdx.x * 16;
    const int t = threadIdx.x;

    #pragma unroll
    for (int i = t; i < 4096; i += 256)
        ((float4*)ws)[i] = ((const float4*)wo)[i];
    #pragma unroll
    for (int i = t; i < 512; i += 256)
        ((float4*)as_)[i] = ((const float4*)(g_attn + (size_t)row0 * DD))[i];
    __syncthreads();

    const int c4 = t & 31;
    const int rg = t >> 5;   // rows rg*2, rg*2+1
    const ulonglong2* W2 = (const ulonglong2*)ws;

    unsigned long long acc[2][2];
    acc[0][0] = acc[0][1] = acc[1][0] = acc[1][1] = 0ull;

    #pragma unroll 8
    for (int d = 0; d < 128; d++) {
        ulonglong2 w = W2[d * 32 + c4];
        #pragma unroll
        for (int r = 0; r < 2; r++) {
            unsigned long long xr = pack2(as_[rg * 2 + r][d]);
            fma2(acc[r][0], xr, w.x);
            fma2(acc[r][1], xr, w.y);
        }
    }
    float4 bb = ((const float4*)bo)[c4];
    #pragma unroll
    for (int r = 0; r < 2; r++) {
        float4 o;
        unpack2(acc[r][0], o.x, o.y);
        unpack2(acc[r][1], o.z, o.w);
        float4 xr = ((const float4*)(x + (size_t)(row0 + rg * 2 + r) * DD))[c4];
        o.x += bb.x + xr.x; o.y += bb.y + xr.y;
        o.z += bb.z + xr.z; o.w += bb.w + xr.w;
        ((float4*)ys[rg * 2 + r])[c4] = o;
    }
    __syncthreads();

    // LayerNorm: 8 warps x 2 rows
    const int wid = t >> 5, lane = t & 31;
    #pragma unroll
    for (int r = 0; r < 2; r++) {
        const int row = wid * 2 + r;
        float4 v = ((float4*)ys[row])[lane];
        float s = v.x + v.y + v.z + v.w;
        #pragma unroll
        for (int o = 16; o > 0; o >>= 1) s += __shfl_xor_sync(0xffffffffu, s, o);
        float mu = s * (1.f / 128.f);
        float dx = v.x - mu, dy = v.y - mu, dz = v.z - mu, dw = v.w - mu;
        float ss = dx * dx + dy * dy + dz * dz + dw * dw;
        #pragma unroll
        for (int o = 16; o > 0; o >>= 1) ss += __shfl_xor_sync(0xffffffffu, ss, o);
        float rstd = rsqrtf(ss * (1.f / 128.f) + 1e-5f);
        float4 gg = ((const float4*)g)[lane];
        float4 bb2 = ((const float4*)bbeta)[lane];
        float4 o4;
        o4.x = dx * rstd * gg.x + bb2.x;
        o4.y = dy * rstd * gg.y + bb2.y;
        o4.z = dz * rstd * gg.z + bb2.z;
        o4.w = dw * rstd * gg.w + bb2.w;
        ((float4*)(out + (size_t)(row0 + row) * DD))[lane] = o4;
    }
}

// ---------------------------------------------------------------------------
extern "C" void kernel_launch(void* const* d_in, const int* in_sizes, int n_in,
                              void* d_out, int out_size)
{
    const float* x    = (const float*)d_in[0];
    const float* st   = (const float*)d_in[1];
    const int*   mask = (const int*)  d_in[2];
    const float* wq   = (const float*)d_in[3];
    const float* bq   = (const float*)d_in[4];
    const float* wk   = (const float*)d_in[5];
    const float* bk   = (const float*)d_in[6];
    const float* wv   = (const float*)d_in[7];
    const float* bv   = (const float*)d_in[8];
    const float* wo   = (const float*)d_in[9];
    const float* bo   = (const float*)d_in[10];
    const float* wst  = (const float*)d_in[11];
    const float* lng  = (const float*)d_in[12];
    const float* lnb  = (const float*)d_in[13];
    float* out = (float*)d_out;

    const int SMEM_BIAS = 4096 + 8 * 2 * SLAB_F * 4;                            // 167936 B
    const int SMEM_QKV  = (128 * 128 + 16 * 128) * 4;                           // 73728 B
    const int SMEM_ATTN = (64 * SC_PITCH + 8 * 128 + 512 + 64 + 128 * 132) * 4; // 206080 B
    const int SMEM_OLN  = (128 * 128 + 16 * 128 + 16 * 128) * 4;                // 81920 B
    cudaFuncSetAttribute(bias_kernel, cudaFuncAttributeMaxDynamicSharedMemorySize, SMEM_BIAS);
    cudaFuncSetAttribute(qkv_kernel,  cudaFuncAttributeMaxDynamicSharedMemorySize, SMEM_QKV);
    cudaFuncSetAttribute(attn_kernel, cudaFuncAttributeMaxDynamicSharedMemorySize, SMEM_ATTN);
    cudaFuncSetAttribute(out_ln_kernel, cudaFuncAttributeMaxDynamicSharedMemorySize, SMEM_OLN);

    bias_kernel<<<BIAS_GRID, 256, SMEM_BIAS>>>(st, wst);
    qkv_kernel<<<dim3(128, 3), 256, SMEM_QKV>>>(x, wq, bq, wk, bk, wv, bv);
    attn_kernel<<<256, 512, SMEM_ATTN>>>(mask);
    out_ln_kernel<<<128, 256, SMEM_OLN>>>(x, wo, bo, lng, lnb, out);
}